// round 4
// baseline (speedup 1.0000x reference)
#include <cuda_runtime.h>
#include <cuda_bf16.h>

typedef unsigned long long u64;

#define NMAX 100000

// ---------------- device scratch (no allocations allowed) ----------------
__device__ float g_agg[NMAX];
__device__ int   g_deg[NMAX];
__device__ float g_tmp[NMAX];
__device__ int   g_degmax;
__device__ float g_sum_agg;
__device__ float g_sum_score;
__device__ float g_sumsq;

// ---------------- packed weight image (u64 = {w[j][2i], w[j][2i+1]}) -----
// K-dimension pair packing. Row bases even (16B aligned).
// Per net (u64 units):
//   SW: 35 rows x 5 kpairs, stride 6          [0, 210)
//   SB: 35 x {b,0} + pad                       [210, 246)
//   HW: 3 x (35 rows x 18 kpairs, stride 18)   [246, 2136)   (K 35->36 zero pad)
//   HB: 3 x 36 x {b,0}                         [2136, 2244)
//   EW: 5 rows x 18 kpairs                     [2244, 2334)
//   EB: 5 x {b,0} + pad                        [2334, 2340)
#define OFF_SW 0
#define OFF_SB 210
#define OFF_HW 246
#define OFF_HB 2136
#define OFF_EW 2244
#define OFF_EB 2334
#define NET_STRIDE 2340
#define WPACK_U64 (2 * NET_STRIDE)   // 4680 u64 = 37440 B

__device__ u64 g_wpack[WPACK_U64];

// ---------------- packed f32x2 helpers ----------------
__device__ __forceinline__ u64 fma2(u64 a, u64 b, u64 c) {
    u64 d;
    asm("fma.rn.f32x2 %0, %1, %2, %3;" : "=l"(d) : "l"(a), "l"(b), "l"(c));
    return d;
}
__device__ __forceinline__ u64 pk(float lo, float hi) {
    return ((u64)__float_as_uint(hi) << 32) | (u64)__float_as_uint(lo);
}
__device__ __forceinline__ float lo32(u64 a) { return __uint_as_float((unsigned)a); }
__device__ __forceinline__ float hi32(u64 a) { return __uint_as_float((unsigned)(a >> 32)); }
__device__ __forceinline__ float sigmoidf(float v) {
    return 1.0f / (1.0f + __expf(-v));
}

// dot of one weight row (KPAIR packed pairs) with packed input, bias preloaded
// in lane0 of binit. Two accumulator chains for ILP.
template<int KPAIR>
__device__ __forceinline__ float rowdot(const u64* __restrict__ wr, u64 binit,
                                        const u64* __restrict__ xin) {
    u64 a0 = binit, a1 = 0ull;
#pragma unroll
    for (int i = 0; i + 1 < KPAIR; i += 2) {
        ulonglong2 w2 = *reinterpret_cast<const ulonglong2*>(wr + i);
        a0 = fma2(w2.x, xin[i],     a0);
        a1 = fma2(w2.y, xin[i + 1], a1);
    }
    if (KPAIR & 1) a0 = fma2(wr[KPAIR - 1], xin[KPAIR - 1], a0);
    return (lo32(a0) + hi32(a0)) + (lo32(a1) + hi32(a1));
}

// One dense layer: NOUT rows, K packed (KPAIR pairs, row stride STRIDE pairs).
// Output written packed: xout[jp] = {y_2jp, y_2jp+1}; odd tail hi-lane = 0.
template<int NOUT, int KPAIR, int STRIDE, bool RELU>
__device__ __forceinline__ void layer(const u64* __restrict__ w,
                                      const u64* __restrict__ b,
                                      const u64* __restrict__ xin,
                                      u64* __restrict__ xout) {
#pragma unroll
    for (int jp = 0; jp < NOUT / 2; jp++) {
        float v0 = rowdot<KPAIR>(w + (2 * jp)     * STRIDE, b[2 * jp],     xin);
        float v1 = rowdot<KPAIR>(w + (2 * jp + 1) * STRIDE, b[2 * jp + 1], xin);
        if (RELU) { v0 = fmaxf(v0, 0.0f); v1 = fmaxf(v1, 0.0f); }
        xout[jp] = pk(v0, v1);
    }
    if (NOUT & 1) {
        float v = rowdot<KPAIR>(w + (NOUT - 1) * STRIDE, b[NOUT - 1], xin);
        if (RELU) v = fmaxf(v, 0.0f);
        xout[NOUT / 2] = pk(v, 0.0f);
    }
}

// ---------------- kernels ----------------
__global__ void zero_kernel(int N) {
    int i = blockIdx.x * blockDim.x + threadIdx.x;
    if (i < N) { g_agg[i] = 0.0f; g_deg[i] = 0; }
}

__global__ void scal_kernel() {
    g_degmax = 0; g_sum_agg = 0.0f; g_sum_score = 0.0f; g_sumsq = 0.0f;
}

// Single block: build the K-pair-packed weight image once.
__global__ void prep_kernel(
    const float* __restrict__ Rsw, const float* __restrict__ Rsb,
    const float* __restrict__ Rhw, const float* __restrict__ Rhb,
    const float* __restrict__ Rew, const float* __restrict__ Reb,
    const float* __restrict__ Psw, const float* __restrict__ Psb,
    const float* __restrict__ Phw, const float* __restrict__ Phb,
    const float* __restrict__ Pew, const float* __restrict__ Peb)
{
    const int t = threadIdx.x, nt = blockDim.x;
    float* wf = reinterpret_cast<float*>(g_wpack);
    for (int k = t; k < 2 * WPACK_U64; k += nt) wf[k] = 0.0f;
    __syncthreads();

    auto putm = [&](const float* __restrict__ s, int offU, int rows, int cols, int stride) {
        int n = rows * cols;
        for (int k = t; k < n; k += nt) {
            int j = k / cols, i = k - j * cols;
            wf[(offU + j * stride + (i >> 1)) * 2 + (i & 1)] = s[k];
        }
    };
    auto putb = [&](const float* __restrict__ s, int offU, int n) {
        for (int j = t; j < n; j += nt)
            wf[(offU + j) * 2] = s[j];              // {b, 0}
    };

    // R net
    putm(Rsw, OFF_SW, 35, 10, 6);
    putb(Rsb, OFF_SB, 35);
    for (int m = 0; m < 3; m++) {
        putm(Rhw + m * 35 * 35, OFF_HW + m * 630, 35, 35, 18);
        putb(Rhb + m * 35,      OFF_HB + m * 36, 35);
    }
    putm(Rew, OFF_EW, 5, 35, 18);   // only first 5 output rows needed
    putb(Reb, OFF_EB, 5);
    // P net
    putm(Psw, NET_STRIDE + OFF_SW, 35, 10, 6);
    putb(Psb, NET_STRIDE + OFF_SB, 35);
    for (int m = 0; m < 3; m++) {
        putm(Phw + m * 35 * 35, NET_STRIDE + OFF_HW + m * 630, 35, 35, 18);
        putb(Phb + m * 35,      NET_STRIDE + OFF_HB + m * 36, 35);
    }
    putm(Pew, NET_STRIDE + OFF_EW, 5, 35, 18);
    putb(Peb, NET_STRIDE + OFF_EB, 5);
}

__global__ void __launch_bounds__(128, 4) edge_kernel(
    const float* __restrict__ score,
    const int*   __restrict__ edge_idx,
    const float* __restrict__ outcome,
    int E)
{
    __shared__ __align__(16) u64 wsm[WPACK_U64];
    const int t = threadIdx.x, nt = blockDim.x;

    // straight vectorized copy of the prepacked image
    {
        const ulonglong2* src = reinterpret_cast<const ulonglong2*>(g_wpack);
        ulonglong2* dst = reinterpret_cast<ulonglong2*>(wsm);
        for (int k = t; k < WPACK_U64 / 2; k += nt) dst[k] = src[k];
    }
    __syncthreads();

    const int e = blockIdx.x * blockDim.x + t;
    if (e >= E) return;

    int idx[10];
    {
        const int2* ei2 = reinterpret_cast<const int2*>(edge_idx + (size_t)e * 10);
#pragma unroll
        for (int k = 0; k < 5; k++) {
            int2 q = ei2[k];
            idx[2 * k] = q.x; idx[2 * k + 1] = q.y;
        }
    }
    float xsc[10];
#pragma unroll
    for (int i = 0; i < 10; i++) xsc[i] = score[idx[i]];

    const bool o = outcome[e] > 0.0f;

#pragma unroll 1
    for (int net = 0; net < 2; net++) {   // 0 = R (+sigmoid), 1 = P (-sigmoid)
        const u64* Wb = wsm + net * NET_STRIDE;
        const bool fwd = (net == 0) ? o : !o;

        u64 xa[18], xb[18];
        // start input: 5 packed pairs, oriented
#pragma unroll
        for (int i = 0; i < 5; i++)
            xa[i] = fwd ? pk(xsc[2 * i], xsc[2 * i + 1])
                        : pk(xsc[9 - 2 * i], xsc[8 - 2 * i]);

        layer<35,  5,  6, true >(Wb + OFF_SW,        Wb + OFF_SB,      xa, xb);
        layer<35, 18, 18, true >(Wb + OFF_HW,        Wb + OFF_HB,      xb, xa);
        layer<35, 18, 18, true >(Wb + OFF_HW +  630, Wb + OFF_HB + 36, xa, xb);
        layer<35, 18, 18, true >(Wb + OFF_HW + 1260, Wb + OFF_HB + 72, xb, xa);
        u64 eo[3];
        layer< 5, 18, 18, false>(Wb + OFF_EW,        Wb + OFF_EB,      xa, eo);

        const float y0 = lo32(eo[0]), y1 = hi32(eo[0]);
        const float y2 = lo32(eo[1]), y3 = hi32(eo[1]);
        const float y4 = lo32(eo[2]);

        const int  base = (net == 0) ? (o ? 0 : 5) : (o ? 5 : 0);
        const float sgn = (net == 0) ? 1.0f : -1.0f;
        atomicAdd(&g_agg[idx[base + 0]], sgn * sigmoidf(y0));
        atomicAdd(&g_agg[idx[base + 1]], sgn * sigmoidf(y1));
        atomicAdd(&g_agg[idx[base + 2]], sgn * sigmoidf(y2));
        atomicAdd(&g_agg[idx[base + 3]], sgn * sigmoidf(y3));
        atomicAdd(&g_agg[idx[base + 4]], sgn * sigmoidf(y4));
    }

#pragma unroll
    for (int k = 0; k < 10; k++) atomicAdd(&g_deg[idx[k]], 1);
}

__device__ __forceinline__ float warp_sum(float v) {
#pragma unroll
    for (int s = 16; s; s >>= 1) v += __shfl_xor_sync(0xffffffffu, v, s);
    return v;
}
__device__ __forceinline__ int warp_max(int v) {
#pragma unroll
    for (int s = 16; s; s >>= 1) v = max(v, __shfl_xor_sync(0xffffffffu, v, s));
    return v;
}

__global__ void reduce1_kernel(const float* __restrict__ score, int N) {
    int i = blockIdx.x * blockDim.x + threadIdx.x;
    int d = 0; float sa = 0.0f, ss = 0.0f;
    if (i < N) { d = g_deg[i]; sa = g_agg[i]; ss = score[i]; }
    sa = warp_sum(sa); ss = warp_sum(ss); d = warp_max(d);
    if ((threadIdx.x & 31) == 0) {
        atomicMax(&g_degmax, d);
        atomicAdd(&g_sum_agg, sa);
        atomicAdd(&g_sum_score, ss);
    }
}

__global__ void reduce2_kernel(const float* __restrict__ score, int N) {
    const float c    = 2.0f / (float)g_degmax;          // NORM_FACTOR / deg.max()
    const float mean = (g_sum_score + c * g_sum_agg) / (float)N;
    int i = blockIdx.x * blockDim.x + threadIdx.x;
    float u = 0.0f;
    if (i < N) { u = score[i] + c * g_agg[i] - mean; g_tmp[i] = u; }
    float sq = warp_sum(u * u);
    if ((threadIdx.x & 31) == 0) atomicAdd(&g_sumsq, sq);
}

__global__ void finalize_kernel(float* __restrict__ out, int N) {
    int i = blockIdx.x * blockDim.x + threadIdx.x;
    if (i < N) out[i] = g_tmp[i] * rsqrtf(g_sumsq);
}

// ---------------- launch ----------------
extern "C" void kernel_launch(void* const* d_in, const int* in_sizes, int n_in,
                              void* d_out, int out_size) {
    const float* score    = (const float*)d_in[0];
    const int*   edge_idx = (const int*)  d_in[1];
    const float* outcome  = (const float*)d_in[2];
    const float* Rsw = (const float*)d_in[3],  *Rsb = (const float*)d_in[4];
    const float* Rhw = (const float*)d_in[5],  *Rhb = (const float*)d_in[6];
    const float* Rew = (const float*)d_in[7],  *Reb = (const float*)d_in[8];
    const float* Psw = (const float*)d_in[9],  *Psb = (const float*)d_in[10];
    const float* Phw = (const float*)d_in[11], *Phb = (const float*)d_in[12];
    const float* Pew = (const float*)d_in[13], *Peb = (const float*)d_in[14];

    const int N = in_sizes[0];   // score is (N, 1)
    const int E = in_sizes[2];   // outcome is (E,)

    const int tb = 256, nb = (N + tb - 1) / tb;
    // launch order chosen so edge_kernel sits at in-call index 3 (the slot
    // ncu has captured in both prior rounds).
    zero_kernel<<<nb, tb>>>(N);                                    // 0
    prep_kernel<<<1, 256>>>(Rsw, Rsb, Rhw, Rhb, Rew, Reb,
                            Psw, Psb, Phw, Phb, Pew, Peb);         // 1
    scal_kernel<<<1, 1>>>();                                       // 2
    edge_kernel<<<(E + 127) / 128, 128>>>(score, edge_idx, outcome, E);  // 3
    reduce1_kernel<<<nb, tb>>>(score, N);                          // 4
    reduce2_kernel<<<nb, tb>>>(score, N);                          // 5
    finalize_kernel<<<nb, tb>>>((float*)d_out, N);                 // 6
}

// round 5
// speedup vs baseline: 4.9400x; 4.9400x over previous
#include <cuda_runtime.h>
#include <cuda_bf16.h>

typedef unsigned long long u64;

#define NMAX 100000

// ---------------- device scratch (no allocations allowed) ----------------
__device__ float g_agg[NMAX];
__device__ int   g_deg[NMAX];
__device__ float g_tmp[NMAX];
__device__ int   g_degmax;
__device__ float g_sum_agg;
__device__ float g_sum_score;
__device__ float g_sumsq;

// ---------------- packed weight image (u64 = {w[j][2i], w[j][2i+1]}) -----
// K-dimension pair packing. Row bases even (16B aligned).
#define OFF_SW 0
#define OFF_SB 210
#define OFF_HW 246
#define OFF_HB 2136
#define OFF_EW 2244
#define OFF_EB 2334
#define NET_STRIDE 2340
#define WPACK_U64 (2 * NET_STRIDE)   // 4680 u64 = 37440 B

__device__ u64 g_wpack[WPACK_U64];

// ---------------- packed f32x2 helpers ----------------
__device__ __forceinline__ u64 fma2(u64 a, u64 b, u64 c) {
    u64 d;
    asm("fma.rn.f32x2 %0, %1, %2, %3;" : "=l"(d) : "l"(a), "l"(b), "l"(c));
    return d;
}
__device__ __forceinline__ u64 pk(float lo, float hi) {
    return ((u64)__float_as_uint(hi) << 32) | (u64)__float_as_uint(lo);
}
__device__ __forceinline__ float lo32(u64 a) { return __uint_as_float((unsigned)a); }
__device__ __forceinline__ float hi32(u64 a) { return __uint_as_float((unsigned)(a >> 32)); }
__device__ __forceinline__ float sigmoidf(float v) {
    return 1.0f / (1.0f + __expf(-v));
}

// dot of one weight row (KPAIR packed pairs) with packed input, bias preloaded
// in lane0 of binit. Two accumulator chains for ILP.
template<int KPAIR>
__device__ __forceinline__ float rowdot(const u64* __restrict__ wr, u64 binit,
                                        const u64* __restrict__ xin) {
    u64 a0 = binit, a1 = 0ull;
#pragma unroll
    for (int i = 0; i + 1 < KPAIR; i += 2) {
        ulonglong2 w2 = *reinterpret_cast<const ulonglong2*>(wr + i);
        a0 = fma2(w2.x, xin[i],     a0);
        a1 = fma2(w2.y, xin[i + 1], a1);
    }
    if (KPAIR & 1) a0 = fma2(wr[KPAIR - 1], xin[KPAIR - 1], a0);
    return (lo32(a0) + hi32(a0)) + (lo32(a1) + hi32(a1));
}

// One dense layer: NOUT rows, K packed (KPAIR pairs, row stride STRIDE pairs).
// Output written packed: xout[jp] = {y_2jp, y_2jp+1}; odd tail hi-lane = 0.
template<int NOUT, int KPAIR, int STRIDE, bool RELU>
__device__ __forceinline__ void layer(const u64* __restrict__ w,
                                      const u64* __restrict__ b,
                                      const u64* __restrict__ xin,
                                      u64* __restrict__ xout) {
#pragma unroll
    for (int jp = 0; jp < NOUT / 2; jp++) {
        float v0 = rowdot<KPAIR>(w + (2 * jp)     * STRIDE, b[2 * jp],     xin);
        float v1 = rowdot<KPAIR>(w + (2 * jp + 1) * STRIDE, b[2 * jp + 1], xin);
        if (RELU) { v0 = fmaxf(v0, 0.0f); v1 = fmaxf(v1, 0.0f); }
        xout[jp] = pk(v0, v1);
    }
    if (NOUT & 1) {
        float v = rowdot<KPAIR>(w + (NOUT - 1) * STRIDE, b[NOUT - 1], xin);
        if (RELU) v = fmaxf(v, 0.0f);
        xout[NOUT / 2] = pk(v, 0.0f);
    }
}

// ---------------- kernels ----------------
__global__ void zero_kernel(int N) {
    int i = blockIdx.x * blockDim.x + threadIdx.x;
    if (i < N) { g_agg[i] = 0.0f; g_deg[i] = 0; }
}

__global__ void scal_kernel() {
    g_degmax = 0; g_sum_agg = 0.0f; g_sum_score = 0.0f; g_sumsq = 0.0f;
}

// Single block: build the K-pair-packed weight image once.
__global__ void prep_kernel(
    const float* __restrict__ Rsw, const float* __restrict__ Rsb,
    const float* __restrict__ Rhw, const float* __restrict__ Rhb,
    const float* __restrict__ Rew, const float* __restrict__ Reb,
    const float* __restrict__ Psw, const float* __restrict__ Psb,
    const float* __restrict__ Phw, const float* __restrict__ Phb,
    const float* __restrict__ Pew, const float* __restrict__ Peb)
{
    const int t = threadIdx.x, nt = blockDim.x;
    float* wf = reinterpret_cast<float*>(g_wpack);
    for (int k = t; k < 2 * WPACK_U64; k += nt) wf[k] = 0.0f;
    __syncthreads();

    auto putm = [&](const float* __restrict__ s, int offU, int rows, int cols, int stride) {
        int n = rows * cols;
        for (int k = t; k < n; k += nt) {
            int j = k / cols, i = k - j * cols;
            wf[(offU + j * stride + (i >> 1)) * 2 + (i & 1)] = s[k];
        }
    };
    auto putb = [&](const float* __restrict__ s, int offU, int n) {
        for (int j = t; j < n; j += nt)
            wf[(offU + j) * 2] = s[j];              // {b, 0}
    };

    // R net
    putm(Rsw, OFF_SW, 35, 10, 6);
    putb(Rsb, OFF_SB, 35);
    for (int m = 0; m < 3; m++) {
        putm(Rhw + m * 35 * 35, OFF_HW + m * 630, 35, 35, 18);
        putb(Rhb + m * 35,      OFF_HB + m * 36, 35);
    }
    putm(Rew, OFF_EW, 5, 35, 18);   // only first 5 output rows needed
    putb(Reb, OFF_EB, 5);
    // P net
    putm(Psw, NET_STRIDE + OFF_SW, 35, 10, 6);
    putb(Psb, NET_STRIDE + OFF_SB, 35);
    for (int m = 0; m < 3; m++) {
        putm(Phw + m * 35 * 35, NET_STRIDE + OFF_HW + m * 630, 35, 35, 18);
        putb(Phb + m * 35,      NET_STRIDE + OFF_HB + m * 36, 35);
    }
    putm(Pew, NET_STRIDE + OFF_EW, 5, 35, 18);
    putb(Peb, NET_STRIDE + OFF_EB, 5);
}

// NOTE: no min-blocks bound — register spills are far more costly here than
// occupancy (FMA pipe saturates with 1 warp/SMSP given 2-chain ILP).
__global__ void __launch_bounds__(128) edge_kernel(
    const float* __restrict__ score,
    const int*   __restrict__ edge_idx,
    const float* __restrict__ outcome,
    int E)
{
    __shared__ __align__(16) u64 wsm[WPACK_U64];
    const int t = threadIdx.x, nt = blockDim.x;

    // straight vectorized copy of the prepacked image
    {
        const ulonglong2* src = reinterpret_cast<const ulonglong2*>(g_wpack);
        ulonglong2* dst = reinterpret_cast<ulonglong2*>(wsm);
        for (int k = t; k < WPACK_U64 / 2; k += nt) dst[k] = src[k];
    }
    __syncthreads();

    const int e = blockIdx.x * blockDim.x + t;
    if (e >= E) return;

    int idx[10];
    {
        const int2* ei2 = reinterpret_cast<const int2*>(edge_idx + (size_t)e * 10);
#pragma unroll
        for (int k = 0; k < 5; k++) {
            int2 q = ei2[k];
            idx[2 * k] = q.x; idx[2 * k + 1] = q.y;
        }
    }
    float xsc[10];
#pragma unroll
    for (int i = 0; i < 10; i++) xsc[i] = score[idx[i]];

    const bool o = outcome[e] > 0.0f;

#pragma unroll 1
    for (int net = 0; net < 2; net++) {   // 0 = R (+sigmoid), 1 = P (-sigmoid)
        const u64* Wb = wsm + net * NET_STRIDE;
        const bool fwd = (net == 0) ? o : !o;

        u64 xa[18], xb[18];
        // start input: 5 packed pairs, oriented
#pragma unroll
        for (int i = 0; i < 5; i++)
            xa[i] = fwd ? pk(xsc[2 * i], xsc[2 * i + 1])
                        : pk(xsc[9 - 2 * i], xsc[8 - 2 * i]);

        layer<35,  5,  6, true >(Wb + OFF_SW,        Wb + OFF_SB,      xa, xb);
        layer<35, 18, 18, true >(Wb + OFF_HW,        Wb + OFF_HB,      xb, xa);
        layer<35, 18, 18, true >(Wb + OFF_HW +  630, Wb + OFF_HB + 36, xa, xb);
        layer<35, 18, 18, true >(Wb + OFF_HW + 1260, Wb + OFF_HB + 72, xb, xa);
        u64 eo[3];
        layer< 5, 18, 18, false>(Wb + OFF_EW,        Wb + OFF_EB,      xa, eo);

        const float y0 = lo32(eo[0]), y1 = hi32(eo[0]);
        const float y2 = lo32(eo[1]), y3 = hi32(eo[1]);
        const float y4 = lo32(eo[2]);

        const int  base = (net == 0) ? (o ? 0 : 5) : (o ? 5 : 0);
        const float sgn = (net == 0) ? 1.0f : -1.0f;
        atomicAdd(&g_agg[idx[base + 0]], sgn * sigmoidf(y0));
        atomicAdd(&g_agg[idx[base + 1]], sgn * sigmoidf(y1));
        atomicAdd(&g_agg[idx[base + 2]], sgn * sigmoidf(y2));
        atomicAdd(&g_agg[idx[base + 3]], sgn * sigmoidf(y3));
        atomicAdd(&g_agg[idx[base + 4]], sgn * sigmoidf(y4));
    }

#pragma unroll
    for (int k = 0; k < 10; k++) atomicAdd(&g_deg[idx[k]], 1);
}

__device__ __forceinline__ float warp_sum(float v) {
#pragma unroll
    for (int s = 16; s; s >>= 1) v += __shfl_xor_sync(0xffffffffu, v, s);
    return v;
}
__device__ __forceinline__ int warp_max(int v) {
#pragma unroll
    for (int s = 16; s; s >>= 1) v = max(v, __shfl_xor_sync(0xffffffffu, v, s));
    return v;
}

__global__ void reduce1_kernel(const float* __restrict__ score, int N) {
    int i = blockIdx.x * blockDim.x + threadIdx.x;
    int d = 0; float sa = 0.0f, ss = 0.0f;
    if (i < N) { d = g_deg[i]; sa = g_agg[i]; ss = score[i]; }
    sa = warp_sum(sa); ss = warp_sum(ss); d = warp_max(d);
    if ((threadIdx.x & 31) == 0) {
        atomicMax(&g_degmax, d);
        atomicAdd(&g_sum_agg, sa);
        atomicAdd(&g_sum_score, ss);
    }
}

__global__ void reduce2_kernel(const float* __restrict__ score, int N) {
    const float c    = 2.0f / (float)g_degmax;          // NORM_FACTOR / deg.max()
    const float mean = (g_sum_score + c * g_sum_agg) / (float)N;
    int i = blockIdx.x * blockDim.x + threadIdx.x;
    float u = 0.0f;
    if (i < N) { u = score[i] + c * g_agg[i] - mean; g_tmp[i] = u; }
    float sq = warp_sum(u * u);
    if ((threadIdx.x & 31) == 0) atomicAdd(&g_sumsq, sq);
}

__global__ void finalize_kernel(float* __restrict__ out, int N) {
    int i = blockIdx.x * blockDim.x + threadIdx.x;
    if (i < N) out[i] = g_tmp[i] * rsqrtf(g_sumsq);
}

// ---------------- launch ----------------
extern "C" void kernel_launch(void* const* d_in, const int* in_sizes, int n_in,
                              void* d_out, int out_size) {
    const float* score    = (const float*)d_in[0];
    const int*   edge_idx = (const int*)  d_in[1];
    const float* outcome  = (const float*)d_in[2];
    const float* Rsw = (const float*)d_in[3],  *Rsb = (const float*)d_in[4];
    const float* Rhw = (const float*)d_in[5],  *Rhb = (const float*)d_in[6];
    const float* Rew = (const float*)d_in[7],  *Reb = (const float*)d_in[8];
    const float* Psw = (const float*)d_in[9],  *Psb = (const float*)d_in[10];
    const float* Phw = (const float*)d_in[11], *Phb = (const float*)d_in[12];
    const float* Pew = (const float*)d_in[13], *Peb = (const float*)d_in[14];

    const int N = in_sizes[0];   // score is (N, 1)
    const int E = in_sizes[2];   // outcome is (E,)

    const int tb = 256, nb = (N + tb - 1) / tb;
    // edge_kernel at in-call index 3 (the slot ncu captures).
    zero_kernel<<<nb, tb>>>(N);                                    // 0
    prep_kernel<<<1, 256>>>(Rsw, Rsb, Rhw, Rhb, Rew, Reb,
                            Psw, Psb, Phw, Phb, Pew, Peb);         // 1
    scal_kernel<<<1, 1>>>();                                       // 2
    edge_kernel<<<(E + 127) / 128, 128>>>(score, edge_idx, outcome, E);  // 3
    reduce1_kernel<<<nb, tb>>>(score, N);                          // 4
    reduce2_kernel<<<nb, tb>>>(score, N);                          // 5
    finalize_kernel<<<nb, tb>>>((float*)d_out, N);                 // 6
}